// round 12
// baseline (speedup 1.0000x reference)
#include <cuda_runtime.h>

// ---------------- static scratch (no dynamic allocation allowed) ------------
#define MAXN 50016
#define MAXE 800000

__device__ float g_H1[MAXN * 64];   // layer-1 features x@W1
__device__ float g_as1[MAXN * 4];   // alpha_src layer1 per head
__device__ float g_ad1[MAXN * 4];   // alpha_dst layer1 per head
__device__ float g_X2[MAXN * 64];   // elu(gat1 output) = input to layer2
__device__ float g_H2[MAXN * 32];   // layer-2 features X2@W2
__device__ float g_as2[MAXN];
__device__ float g_ad2[MAXN];
__device__ int   g_deg[MAXN];       // zero at load; re-zeroed in scan each run
__device__ int   g_rowptr[MAXN + 1];
__device__ int   g_wpos[MAXN + 1];
__device__ int   g_csrsrc[MAXE];
__device__ float4 g_w1[MAXE];       // layer-1 edge weights (4 heads), CSR order
__device__ int   g_bsums[64];
__device__ float g_v2s[64];         // W2@a_src2
__device__ float g_v2d[64];         // W2@a_dst2
__device__ int   g_cnt1;            // scan barrier counters (self-resetting)
__device__ int   g_cnt2;

// ---------------- L1: fused GEMM1 (+alpha epilogue) ⊕ edge histogram --------
__global__ void k_gemm1_hist(const float* __restrict__ x, const float* __restrict__ W1,
                             const float* __restrict__ a_src, const float* __restrict__ a_dst,
                             const int* __restrict__ ei, int N, int E, int gemmBlocks) {
    __shared__ float Wsh[128 * 64];   // 32 KB
    __shared__ float xs[128][17];

    if (blockIdx.x >= gemmBlocks) {
        int nb = gridDim.x - gemmBlocks;
        int stride = nb * blockDim.x;
        for (int e = (blockIdx.x - gemmBlocks) * blockDim.x + threadIdx.x; e < E; e += stride)
            atomicAdd(&g_deg[ei[E + e]], 1);
        return;
    }

    int t = threadIdx.x;
    int n0 = blockIdx.x * 128;
    for (int i = t; i < 128 * 64; i += 256) Wsh[i] = W1[i];

    int ng = t >> 3;
    int cg = t & 7;
    float acc[4][8];
#pragma unroll
    for (int r = 0; r < 4; ++r)
#pragma unroll
        for (int j = 0; j < 8; ++j) acc[r][j] = 0.f;

    for (int kt = 0; kt < 128; kt += 16) {
        __syncthreads();
        for (int i = t; i < 128 * 16; i += 256) {
            int n = i >> 4, kk = i & 15;
            int gn = n0 + n;
            xs[n][kk] = (gn < N) ? x[gn * 128 + kt + kk] : 0.f;
        }
        __syncthreads();
#pragma unroll
        for (int kk = 0; kk < 16; ++kk) {
            float wv[8];
#pragma unroll
            for (int j = 0; j < 8; ++j) wv[j] = Wsh[(kt + kk) * 64 + cg * 8 + j];
#pragma unroll
            for (int r = 0; r < 4; ++r) {
                float xv = xs[ng * 4 + r][kk];
#pragma unroll
                for (int j = 0; j < 8; ++j) acc[r][j] = fmaf(xv, wv[j], acc[r][j]);
            }
        }
    }

    float asw[8], adw[8];
#pragma unroll
    for (int j = 0; j < 8; ++j) { asw[j] = __ldg(&a_src[cg * 8 + j]); adw[j] = __ldg(&a_dst[cg * 8 + j]); }

#pragma unroll
    for (int r = 0; r < 4; ++r) {
        int gn = n0 + ng * 4 + r;
        float ps = 0.f, pd = 0.f;
#pragma unroll
        for (int j = 0; j < 8; ++j) { ps = fmaf(acc[r][j], asw[j], ps); pd = fmaf(acc[r][j], adw[j], pd); }
        ps += __shfl_xor_sync(0xffffffffu, ps, 1);
        pd += __shfl_xor_sync(0xffffffffu, pd, 1);
        if (gn < N) {
            float4* dst = reinterpret_cast<float4*>(&g_H1[gn * 64 + cg * 8]);
            dst[0] = make_float4(acc[r][0], acc[r][1], acc[r][2], acc[r][3]);
            dst[1] = make_float4(acc[r][4], acc[r][5], acc[r][6], acc[r][7]);
            if ((cg & 1) == 0) {
                g_as1[gn * 4 + (cg >> 1)] = ps;
                g_ad1[gn * 4 + (cg >> 1)] = pd;
            }
        }
    }
}

// ---------------- L2: single-launch scan (device barrier) ⊕ vpre -------------
__global__ void k_scan_fused(const float* __restrict__ W2,
                             const float* __restrict__ a_src2, const float* __restrict__ a_dst2,
                             int N, int nb) {
    int t = threadIdx.x;
    int bid = blockIdx.x;
    if (bid == nb) {
        if (t < 64) {
            float s2 = 0.f, d2 = 0.f;
#pragma unroll
            for (int j = 0; j < 32; ++j) {
                float wv = W2[t * 32 + j];
                s2 = fmaf(wv, a_src2[j], s2);
                d2 = fmaf(wv, a_dst2[j], d2);
            }
            g_v2s[t] = s2;
            g_v2d[t] = d2;
        }
        return;
    }

    __shared__ int wsum[32];
    __shared__ int sh_off;
    int lane = t & 31, wid = t >> 5;
    int i = bid * 1024 + t;
    int v = (i < N) ? g_deg[i] : 0;
    if (i < N) g_deg[i] = 0;
    int xx = v;
#pragma unroll
    for (int o = 1; o < 32; o <<= 1) {
        int u = __shfl_up_sync(0xffffffffu, xx, o);
        if (lane >= o) xx += u;
    }
    if (lane == 31) wsum[wid] = xx;
    __syncthreads();
    if (wid == 0) {
        int w = wsum[lane];
#pragma unroll
        for (int o = 1; o < 32; o <<= 1) {
            int u = __shfl_up_sync(0xffffffffu, w, o);
            if (lane >= o) w += u;
        }
        wsum[lane] = w;
    }
    __syncthreads();
    int woff = (wid > 0) ? wsum[wid - 1] : 0;
    int incl = woff + xx;

    if (t == 1023) {
        g_bsums[bid] = incl;
        __threadfence();
        atomicAdd(&g_cnt1, 1);
    }
    if (t == 0) {
        while (*(volatile int*)&g_cnt1 < nb) {}
    }
    __syncthreads();
    __threadfence();

    if (t < 32) {
        int l = t;
        int v1 = (l < nb) ? g_bsums[l] : 0;
        int v2 = (l + 32 < nb) ? g_bsums[l + 32] : 0;
#pragma unroll
        for (int o = 1; o < 32; o <<= 1) {
            int u = __shfl_up_sync(0xffffffffu, v1, o);
            if (l >= o) v1 += u;
        }
        int tot1 = __shfl_sync(0xffffffffu, v1, 31);
#pragma unroll
        for (int o = 1; o < 32; o <<= 1) {
            int u = __shfl_up_sync(0xffffffffu, v2, o);
            if (l >= o) v2 += u;
        }
        int ex;
        if (bid == 0) ex = 0;
        else if (bid - 1 < 32) ex = __shfl_sync(0xffffffffu, v1, bid - 1);
        else ex = tot1 + __shfl_sync(0xffffffffu, v2, bid - 1 - 32);
        if (l == 0) sh_off = ex;
    }
    __syncthreads();
    int off = sh_off;
    if (i < N) {
        int val = incl + off;
        g_rowptr[i + 1] = val;
        g_wpos[i + 1] = val;
    }
    if (bid == 0 && t == 0) { g_rowptr[0] = 0; g_wpos[0] = 0; }

    __syncthreads();
    if (t == 0) {
        int done = atomicAdd(&g_cnt2, 1);
        if (done == nb - 1) { g_cnt1 = 0; g_cnt2 = 0; }
    }
}

// ---------------- L3: CSR fill + layer-1 edge weights ------------------------
__global__ void __launch_bounds__(256) k_fillw(const int* __restrict__ ei, int E) {
    int e = blockIdx.x * blockDim.x + threadIdx.x;
    if (e >= E) return;
    int src = ei[e];
    int dst = ei[E + e];
    int p = atomicAdd(&g_wpos[dst], 1);
    g_csrsrc[p] = src;
    float4 as = __ldg(reinterpret_cast<const float4*>(&g_as1[src * 4]));
    float4 ad = __ldg(reinterpret_cast<const float4*>(&g_ad1[dst * 4]));
    float4 w;
    float e0 = as.x + ad.x; w.x = __expf(fmaxf(e0, 0.2f * e0));
    float e1 = as.y + ad.y; w.y = __expf(fmaxf(e1, 0.2f * e1));
    float e2 = as.z + ad.z; w.z = __expf(fmaxf(e2, 0.2f * e2));
    float e3 = as.w + ad.w; w.w = __expf(fmaxf(e3, 0.2f * e3));
    g_w1[p] = w;
}

// ---------------- L4: layer-1 agg: quarter-warp, LINE-COALESCED gather -------
// lane hl (0..7) covers channels [hl*4, hl*4+4) and [32+hl*4, 32+hl*4+4):
// each LDG.128 maps one 8-lane group onto exactly one 128B line.
// heads: first vec -> head hl>>2 (0/1), second vec -> head 2+(hl>>2) (2/3).
__global__ void k_agg1(const float* __restrict__ b1, int N) {
    int warp = (blockIdx.x * blockDim.x + threadIdx.x) >> 5;
    int lane = threadIdx.x & 31;
    int q = lane >> 3;          // node slot 0..3
    int hl = lane & 7;          // lane-in-group 0..7
    unsigned gmask = 0xffu << (q * 8);
    int node = warp * 4 + q;
    if (node >= N) return;
    int beg = g_rowptr[node], end = g_rowptr[node + 1];
    int chA = hl * 4;           // channels in heads 0/1
    int chB = 32 + hl * 4;      // channels in heads 2/3
    bool lo = (hl < 4);         // head A = lo?0:1, head B = lo?2:3

    float sA = 0.f, sB = 0.f;
    float a[8] = {0, 0, 0, 0, 0, 0, 0, 0};
    for (int p = beg; p < end; ++p) {
        int src = g_csrsrc[p];
        float4 wv = __ldg(&g_w1[p]);                 // broadcast within group
        float wA = lo ? wv.x : wv.y;
        float wB = lo ? wv.z : wv.w;
        float4 h0 = *reinterpret_cast<const float4*>(&g_H1[src * 64 + chA]);
        float4 h1 = *reinterpret_cast<const float4*>(&g_H1[src * 64 + chB]);
        sA += wA;
        sB += wB;
        a[0] = fmaf(wA, h0.x, a[0]);
        a[1] = fmaf(wA, h0.y, a[1]);
        a[2] = fmaf(wA, h0.z, a[2]);
        a[3] = fmaf(wA, h0.w, a[3]);
        a[4] = fmaf(wB, h1.x, a[4]);
        a[5] = fmaf(wB, h1.y, a[5]);
        a[6] = fmaf(wB, h1.z, a[6]);
        a[7] = fmaf(wB, h1.w, a[7]);
    }
    float invA = 1.f / (sA + 1e-16f);
    float invB = 1.f / (sB + 1e-16f);
    float4 bbA = *reinterpret_cast<const float4*>(&b1[chA]);
    float4 bbB = *reinterpret_cast<const float4*>(&b1[chB]);
    float o[8];
    o[0] = fmaf(a[0], invA, bbA.x); o[1] = fmaf(a[1], invA, bbA.y);
    o[2] = fmaf(a[2], invA, bbA.z); o[3] = fmaf(a[3], invA, bbA.w);
    o[4] = fmaf(a[4], invB, bbB.x); o[5] = fmaf(a[5], invB, bbB.y);
    o[6] = fmaf(a[6], invB, bbB.z); o[7] = fmaf(a[7], invB, bbB.w);
#pragma unroll
    for (int j = 0; j < 8; ++j) o[j] = (o[j] > 0.f) ? o[j] : expm1f(o[j]);   // elu
    *reinterpret_cast<float4*>(&g_X2[node * 64 + chA]) = make_float4(o[0], o[1], o[2], o[3]);
    *reinterpret_cast<float4*>(&g_X2[node * 64 + chB]) = make_float4(o[4], o[5], o[6], o[7]);

    // epilogue: as2/ad2 = X2row . v2 (8-lane group reduction over split channels)
    float4 vsA = *reinterpret_cast<const float4*>(&g_v2s[chA]);
    float4 vsB = *reinterpret_cast<const float4*>(&g_v2s[chB]);
    float4 vdA = *reinterpret_cast<const float4*>(&g_v2d[chA]);
    float4 vdB = *reinterpret_cast<const float4*>(&g_v2d[chB]);
    float ps = o[0]*vsA.x + o[1]*vsA.y + o[2]*vsA.z + o[3]*vsA.w
             + o[4]*vsB.x + o[5]*vsB.y + o[6]*vsB.z + o[7]*vsB.w;
    float pd = o[0]*vdA.x + o[1]*vdA.y + o[2]*vdA.z + o[3]*vdA.w
             + o[4]*vdB.x + o[5]*vdB.y + o[6]*vdB.z + o[7]*vdB.w;
#pragma unroll
    for (int off = 1; off < 8; off <<= 1) {
        ps += __shfl_xor_sync(gmask, ps, off);
        pd += __shfl_xor_sync(gmask, pd, off);
    }
    if (hl == 0) { g_as2[node] = ps; g_ad2[node] = pd; }
}

// ---------------- L5: GEMM2 ---------------------------------------------------
__global__ void k_gemm2(const float* __restrict__ W2, int N) {
    __shared__ float Wsh[64 * 32];
    __shared__ float xs[128][65];
    int t = threadIdx.x;
    int n0 = blockIdx.x * 128;
    for (int i = t; i < 64 * 32; i += 128) Wsh[i] = W2[i];
    for (int i = t; i < 128 * 64; i += 128) {
        int n = i >> 6, k = i & 63;
        int gn = n0 + n;
        xs[n][k] = (gn < N) ? g_X2[gn * 64 + k] : 0.f;
    }
    __syncthreads();
    int ng = t >> 2;
    int cg = t & 3;
    float acc[4][8];
#pragma unroll
    for (int r = 0; r < 4; ++r)
#pragma unroll
        for (int j = 0; j < 8; ++j) acc[r][j] = 0.f;
#pragma unroll 4
    for (int k = 0; k < 64; ++k) {
        float wv[8];
#pragma unroll
        for (int j = 0; j < 8; ++j) wv[j] = Wsh[k * 32 + cg * 8 + j];
#pragma unroll
        for (int r = 0; r < 4; ++r) {
            float xv = xs[ng * 4 + r][k];
#pragma unroll
            for (int j = 0; j < 8; ++j) acc[r][j] = fmaf(xv, wv[j], acc[r][j]);
        }
    }
#pragma unroll
    for (int r = 0; r < 4; ++r) {
        int gn = n0 + ng * 4 + r;
        if (gn < N) {
            float4* dst = reinterpret_cast<float4*>(&g_H2[gn * 32 + cg * 8]);
            dst[0] = make_float4(acc[r][0], acc[r][1], acc[r][2], acc[r][3]);
            dst[1] = make_float4(acc[r][4], acc[r][5], acc[r][6], acc[r][7]);
        }
    }
}

// ---------------- L6: layer-2 agg: quarter-warp (already line-coalesced) -----
__global__ void k_agg2(const float* __restrict__ b2, float* __restrict__ out, int N) {
    int warp = (blockIdx.x * blockDim.x + threadIdx.x) >> 5;
    int lane = threadIdx.x & 31;
    int q = lane >> 3;
    int hl = lane & 7;
    int node = warp * 4 + q;
    if (node >= N) return;
    int beg = g_rowptr[node], end = g_rowptr[node + 1];
    int ch = hl * 4;
    float adv = g_ad2[node];

    float s = 0.f;
    float a0 = 0.f, a1 = 0.f, a2 = 0.f, a3 = 0.f;
    for (int p = beg; p < end; ++p) {
        int src = g_csrsrc[p];
        float e = __ldg(&g_as2[src]) + adv;
        float4 h = *reinterpret_cast<const float4*>(&g_H2[src * 32 + ch]);
        float w = __expf(fmaxf(e, 0.2f * e));
        s += w;
        a0 = fmaf(w, h.x, a0);
        a1 = fmaf(w, h.y, a1);
        a2 = fmaf(w, h.z, a2);
        a3 = fmaf(w, h.w, a3);
    }
    float inv = 1.f / (s + 1e-16f);
    float4 bb = *reinterpret_cast<const float4*>(&b2[ch]);
    float4 o;
    o.x = fmaf(a0, inv, bb.x);
    o.y = fmaf(a1, inv, bb.y);
    o.z = fmaf(a2, inv, bb.z);
    o.w = fmaf(a3, inv, bb.w);
    *reinterpret_cast<float4*>(&out[node * 32 + ch]) = o;
}

// ---------------- launch -----------------------------------------------------
extern "C" void kernel_launch(void* const* d_in, const int* in_sizes, int n_in,
                              void* d_out, int out_size) {
    const float* x      = (const float*)d_in[0];
    const int*   ei     = (const int*)  d_in[1];
    const float* W1     = (const float*)d_in[2];
    const float* a_src1 = (const float*)d_in[3];
    const float* a_dst1 = (const float*)d_in[4];
    const float* b1     = (const float*)d_in[5];
    const float* W2     = (const float*)d_in[6];
    const float* a_src2 = (const float*)d_in[7];
    const float* a_dst2 = (const float*)d_in[8];
    const float* b2     = (const float*)d_in[9];

    int N = in_sizes[0] / 128;
    int E = in_sizes[1] / 2;
    int nb = (N + 1023) / 1024;

    int gemmBlocks = (N + 127) / 128;
    int histBlocks = 1184;
    int aggWarps = (N + 3) / 4;          // 4 nodes per warp

    // L1: GEMM1(+alphas1) overlapped with edge histogram
    k_gemm1_hist<<<gemmBlocks + histBlocks, 256>>>(x, W1, a_src1, a_dst1, ei, N, E, gemmBlocks);
    // L2: single-launch scan (device barrier) + v2 projections
    k_scan_fused<<<nb + 1, 1024>>>(W2, a_src2, a_dst2, N, nb);
    // L3: CSR fill + layer-1 edge weights
    k_fillw<<<(E + 255) / 256, 256>>>(ei, E);
    // L4: layer-1 aggregation (+elu, +as2/ad2)
    k_agg1<<<(aggWarps * 32 + 255) / 256, 256>>>(b1, N);
    // L5: GEMM2
    k_gemm2<<<(N + 127) / 128, 128>>>(W2, N);
    // L6: layer-2 aggregation (inline w2)
    k_agg2<<<(aggWarps * 32 + 255) / 256, 256>>>(b2, (float*)d_out, N);
}

// round 13
// speedup vs baseline: 1.0022x; 1.0022x over previous
#include <cuda_runtime.h>

// ---------------- static scratch (no dynamic allocation allowed) ------------
#define MAXN 50016
#define MAXE 800000

__device__ float g_H1[MAXN * 64];   // layer-1 features x@W1
__device__ float g_as1[MAXN * 4];   // alpha_src layer1 per head
__device__ float g_ad1[MAXN * 4];   // alpha_dst layer1 per head
__device__ float g_X2[MAXN * 64];   // elu(gat1 output) = input to layer2
__device__ float g_H2[MAXN * 32];   // layer-2 features X2@W2
__device__ float g_as2[MAXN];
__device__ float g_ad2[MAXN];
__device__ int   g_deg[MAXN];       // zero at load; re-zeroed in scan each run
__device__ int   g_rowptr[MAXN + 1];
__device__ int   g_wpos[MAXN + 1];
__device__ int   g_csrsrc[MAXE];
__device__ float4 g_w1[MAXE];       // layer-1 edge weights (4 heads), CSR order
__device__ int   g_bsums[64];
__device__ float g_v2s[64];         // W2@a_src2
__device__ float g_v2d[64];         // W2@a_dst2
__device__ int   g_cnt1;            // scan barrier counters (self-resetting)
__device__ int   g_cnt2;

// ---------------- L1: fused GEMM1 (+alpha epilogue) ⊕ edge histogram --------
__global__ void k_gemm1_hist(const float* __restrict__ x, const float* __restrict__ W1,
                             const float* __restrict__ a_src, const float* __restrict__ a_dst,
                             const int* __restrict__ ei, int N, int E, int gemmBlocks) {
    __shared__ float Wsh[128 * 64];   // 32 KB
    __shared__ float xs[128][17];

    if (blockIdx.x >= gemmBlocks) {
        int nb = gridDim.x - gemmBlocks;
        int stride = nb * blockDim.x;
        for (int e = (blockIdx.x - gemmBlocks) * blockDim.x + threadIdx.x; e < E; e += stride)
            atomicAdd(&g_deg[ei[E + e]], 1);
        return;
    }

    int t = threadIdx.x;
    int n0 = blockIdx.x * 128;
    for (int i = t; i < 128 * 64; i += 256) Wsh[i] = W1[i];

    int ng = t >> 3;
    int cg = t & 7;
    float acc[4][8];
#pragma unroll
    for (int r = 0; r < 4; ++r)
#pragma unroll
        for (int j = 0; j < 8; ++j) acc[r][j] = 0.f;

    for (int kt = 0; kt < 128; kt += 16) {
        __syncthreads();
        for (int i = t; i < 128 * 16; i += 256) {
            int n = i >> 4, kk = i & 15;
            int gn = n0 + n;
            xs[n][kk] = (gn < N) ? x[gn * 128 + kt + kk] : 0.f;
        }
        __syncthreads();
#pragma unroll
        for (int kk = 0; kk < 16; ++kk) {
            float wv[8];
#pragma unroll
            for (int j = 0; j < 8; ++j) wv[j] = Wsh[(kt + kk) * 64 + cg * 8 + j];
#pragma unroll
            for (int r = 0; r < 4; ++r) {
                float xv = xs[ng * 4 + r][kk];
#pragma unroll
                for (int j = 0; j < 8; ++j) acc[r][j] = fmaf(xv, wv[j], acc[r][j]);
            }
        }
    }

    float asw[8], adw[8];
#pragma unroll
    for (int j = 0; j < 8; ++j) { asw[j] = __ldg(&a_src[cg * 8 + j]); adw[j] = __ldg(&a_dst[cg * 8 + j]); }

#pragma unroll
    for (int r = 0; r < 4; ++r) {
        int gn = n0 + ng * 4 + r;
        float ps = 0.f, pd = 0.f;
#pragma unroll
        for (int j = 0; j < 8; ++j) { ps = fmaf(acc[r][j], asw[j], ps); pd = fmaf(acc[r][j], adw[j], pd); }
        ps += __shfl_xor_sync(0xffffffffu, ps, 1);
        pd += __shfl_xor_sync(0xffffffffu, pd, 1);
        if (gn < N) {
            float4* dst = reinterpret_cast<float4*>(&g_H1[gn * 64 + cg * 8]);
            dst[0] = make_float4(acc[r][0], acc[r][1], acc[r][2], acc[r][3]);
            dst[1] = make_float4(acc[r][4], acc[r][5], acc[r][6], acc[r][7]);
            if ((cg & 1) == 0) {
                g_as1[gn * 4 + (cg >> 1)] = ps;
                g_ad1[gn * 4 + (cg >> 1)] = pd;
            }
        }
    }
}

// ---------------- L2: single-launch scan (device barrier) ⊕ vpre -------------
__global__ void k_scan_fused(const float* __restrict__ W2,
                             const float* __restrict__ a_src2, const float* __restrict__ a_dst2,
                             int N, int nb) {
    int t = threadIdx.x;
    int bid = blockIdx.x;
    if (bid == nb) {
        if (t < 64) {
            float s2 = 0.f, d2 = 0.f;
#pragma unroll
            for (int j = 0; j < 32; ++j) {
                float wv = W2[t * 32 + j];
                s2 = fmaf(wv, a_src2[j], s2);
                d2 = fmaf(wv, a_dst2[j], d2);
            }
            g_v2s[t] = s2;
            g_v2d[t] = d2;
        }
        return;
    }

    __shared__ int wsum[32];
    __shared__ int sh_off;
    int lane = t & 31, wid = t >> 5;
    int i = bid * 1024 + t;
    int v = (i < N) ? g_deg[i] : 0;
    if (i < N) g_deg[i] = 0;
    int xx = v;
#pragma unroll
    for (int o = 1; o < 32; o <<= 1) {
        int u = __shfl_up_sync(0xffffffffu, xx, o);
        if (lane >= o) xx += u;
    }
    if (lane == 31) wsum[wid] = xx;
    __syncthreads();
    if (wid == 0) {
        int w = wsum[lane];
#pragma unroll
        for (int o = 1; o < 32; o <<= 1) {
            int u = __shfl_up_sync(0xffffffffu, w, o);
            if (lane >= o) w += u;
        }
        wsum[lane] = w;
    }
    __syncthreads();
    int woff = (wid > 0) ? wsum[wid - 1] : 0;
    int incl = woff + xx;

    if (t == 1023) {
        g_bsums[bid] = incl;
        __threadfence();
        atomicAdd(&g_cnt1, 1);
    }
    if (t == 0) {
        while (*(volatile int*)&g_cnt1 < nb) {}
    }
    __syncthreads();
    __threadfence();

    if (t < 32) {
        int l = t;
        int v1 = (l < nb) ? g_bsums[l] : 0;
        int v2 = (l + 32 < nb) ? g_bsums[l + 32] : 0;
#pragma unroll
        for (int o = 1; o < 32; o <<= 1) {
            int u = __shfl_up_sync(0xffffffffu, v1, o);
            if (l >= o) v1 += u;
        }
        int tot1 = __shfl_sync(0xffffffffu, v1, 31);
#pragma unroll
        for (int o = 1; o < 32; o <<= 1) {
            int u = __shfl_up_sync(0xffffffffu, v2, o);
            if (l >= o) v2 += u;
        }
        int ex;
        if (bid == 0) ex = 0;
        else if (bid - 1 < 32) ex = __shfl_sync(0xffffffffu, v1, bid - 1);
        else ex = tot1 + __shfl_sync(0xffffffffu, v2, bid - 1 - 32);
        if (l == 0) sh_off = ex;
    }
    __syncthreads();
    int off = sh_off;
    if (i < N) {
        int val = incl + off;
        g_rowptr[i + 1] = val;
        g_wpos[i + 1] = val;
    }
    if (bid == 0 && t == 0) { g_rowptr[0] = 0; g_wpos[0] = 0; }

    __syncthreads();
    if (t == 0) {
        int done = atomicAdd(&g_cnt2, 1);
        if (done == nb - 1) { g_cnt1 = 0; g_cnt2 = 0; }
    }
}

// ---------------- L3: CSR fill + layer-1 edge weights ------------------------
__global__ void __launch_bounds__(256) k_fillw(const int* __restrict__ ei, int E) {
    int e = blockIdx.x * blockDim.x + threadIdx.x;
    if (e >= E) return;
    int src = ei[e];
    int dst = ei[E + e];
    int p = atomicAdd(&g_wpos[dst], 1);
    g_csrsrc[p] = src;
    float4 as = __ldg(reinterpret_cast<const float4*>(&g_as1[src * 4]));
    float4 ad = __ldg(reinterpret_cast<const float4*>(&g_ad1[dst * 4]));
    float4 w;
    float e0 = as.x + ad.x; w.x = __expf(fmaxf(e0, 0.2f * e0));
    float e1 = as.y + ad.y; w.y = __expf(fmaxf(e1, 0.2f * e1));
    float e2 = as.z + ad.z; w.z = __expf(fmaxf(e2, 0.2f * e2));
    float e3 = as.w + ad.w; w.w = __expf(fmaxf(e3, 0.2f * e3));
    g_w1[p] = w;
}

// ---------------- L4: layer-1 agg: quarter-warp, x2-unrolled -----------------
// R11 channel map (measured 27.4us) + 2-edge software pipeline for MLP.
__global__ void k_agg1(const float* __restrict__ b1, int N) {
    int warp = (blockIdx.x * blockDim.x + threadIdx.x) >> 5;
    int lane = threadIdx.x & 31;
    int q = lane >> 3;          // node slot 0..3
    int hl = lane & 7;          // lane-in-group 0..7
    unsigned gmask = 0xffu << (q * 8);
    int node = warp * 4 + q;
    if (node >= N) return;
    int beg = g_rowptr[node], end = g_rowptr[node + 1];
    int ch = hl * 8;            // 8 channels per lane
    int head = hl >> 1;         // 16 channels per head
    const float* w1f = reinterpret_cast<const float*>(g_w1);

    float s = 0.f;
    float a[8] = {0, 0, 0, 0, 0, 0, 0, 0};
    int p = beg;
    for (; p + 1 < end; p += 2) {
        int s0 = g_csrsrc[p];
        int s1 = g_csrsrc[p + 1];
        float w0 = __ldg(&w1f[p * 4 + head]);
        float w1v = __ldg(&w1f[(p + 1) * 4 + head]);
        const float4* hp0 = reinterpret_cast<const float4*>(&g_H1[s0 * 64 + ch]);
        const float4* hp1 = reinterpret_cast<const float4*>(&g_H1[s1 * 64 + ch]);
        float4 hA0 = hp0[0], hA1 = hp0[1];
        float4 hB0 = hp1[0], hB1 = hp1[1];
        s += w0;
        a[0] = fmaf(w0, hA0.x, a[0]);
        a[1] = fmaf(w0, hA0.y, a[1]);
        a[2] = fmaf(w0, hA0.z, a[2]);
        a[3] = fmaf(w0, hA0.w, a[3]);
        a[4] = fmaf(w0, hA1.x, a[4]);
        a[5] = fmaf(w0, hA1.y, a[5]);
        a[6] = fmaf(w0, hA1.z, a[6]);
        a[7] = fmaf(w0, hA1.w, a[7]);
        s += w1v;
        a[0] = fmaf(w1v, hB0.x, a[0]);
        a[1] = fmaf(w1v, hB0.y, a[1]);
        a[2] = fmaf(w1v, hB0.z, a[2]);
        a[3] = fmaf(w1v, hB0.w, a[3]);
        a[4] = fmaf(w1v, hB1.x, a[4]);
        a[5] = fmaf(w1v, hB1.y, a[5]);
        a[6] = fmaf(w1v, hB1.z, a[6]);
        a[7] = fmaf(w1v, hB1.w, a[7]);
    }
    if (p < end) {
        int s0 = g_csrsrc[p];
        float w0 = __ldg(&w1f[p * 4 + head]);
        const float4* hp0 = reinterpret_cast<const float4*>(&g_H1[s0 * 64 + ch]);
        float4 hA0 = hp0[0], hA1 = hp0[1];
        s += w0;
        a[0] = fmaf(w0, hA0.x, a[0]);
        a[1] = fmaf(w0, hA0.y, a[1]);
        a[2] = fmaf(w0, hA0.z, a[2]);
        a[3] = fmaf(w0, hA0.w, a[3]);
        a[4] = fmaf(w0, hA1.x, a[4]);
        a[5] = fmaf(w0, hA1.y, a[5]);
        a[6] = fmaf(w0, hA1.z, a[6]);
        a[7] = fmaf(w0, hA1.w, a[7]);
    }
    float inv = 1.f / (s + 1e-16f);
    float4 bb0 = *reinterpret_cast<const float4*>(&b1[ch]);
    float4 bb1 = *reinterpret_cast<const float4*>(&b1[ch + 4]);
    float o[8];
    o[0] = fmaf(a[0], inv, bb0.x); o[1] = fmaf(a[1], inv, bb0.y);
    o[2] = fmaf(a[2], inv, bb0.z); o[3] = fmaf(a[3], inv, bb0.w);
    o[4] = fmaf(a[4], inv, bb1.x); o[5] = fmaf(a[5], inv, bb1.y);
    o[6] = fmaf(a[6], inv, bb1.z); o[7] = fmaf(a[7], inv, bb1.w);
#pragma unroll
    for (int j = 0; j < 8; ++j) o[j] = (o[j] > 0.f) ? o[j] : expm1f(o[j]);   // elu
    float4* xo = reinterpret_cast<float4*>(&g_X2[node * 64 + ch]);
    xo[0] = make_float4(o[0], o[1], o[2], o[3]);
    xo[1] = make_float4(o[4], o[5], o[6], o[7]);

    // epilogue: as2/ad2 = X2row . v2 (8-lane group reduction)
    const float4* vsp = reinterpret_cast<const float4*>(&g_v2s[ch]);
    const float4* vdp = reinterpret_cast<const float4*>(&g_v2d[ch]);
    float4 vs0 = vsp[0], vs1 = vsp[1], vd0 = vdp[0], vd1 = vdp[1];
    float ps = o[0]*vs0.x + o[1]*vs0.y + o[2]*vs0.z + o[3]*vs0.w
             + o[4]*vs1.x + o[5]*vs1.y + o[6]*vs1.z + o[7]*vs1.w;
    float pd = o[0]*vd0.x + o[1]*vd0.y + o[2]*vd0.z + o[3]*vd0.w
             + o[4]*vd1.x + o[5]*vd1.y + o[6]*vd1.z + o[7]*vd1.w;
#pragma unroll
    for (int off = 1; off < 8; off <<= 1) {
        ps += __shfl_xor_sync(gmask, ps, off);
        pd += __shfl_xor_sync(gmask, pd, off);
    }
    if (hl == 0) { g_as2[node] = ps; g_ad2[node] = pd; }
}

// ---------------- L5: GEMM2 ---------------------------------------------------
__global__ void k_gemm2(const float* __restrict__ W2, int N) {
    __shared__ float Wsh[64 * 32];
    __shared__ float xs[128][65];
    int t = threadIdx.x;
    int n0 = blockIdx.x * 128;
    for (int i = t; i < 64 * 32; i += 128) Wsh[i] = W2[i];
    for (int i = t; i < 128 * 64; i += 128) {
        int n = i >> 6, k = i & 63;
        int gn = n0 + n;
        xs[n][k] = (gn < N) ? g_X2[gn * 64 + k] : 0.f;
    }
    __syncthreads();
    int ng = t >> 2;
    int cg = t & 3;
    float acc[4][8];
#pragma unroll
    for (int r = 0; r < 4; ++r)
#pragma unroll
        for (int j = 0; j < 8; ++j) acc[r][j] = 0.f;
#pragma unroll 4
    for (int k = 0; k < 64; ++k) {
        float wv[8];
#pragma unroll
        for (int j = 0; j < 8; ++j) wv[j] = Wsh[k * 32 + cg * 8 + j];
#pragma unroll
        for (int r = 0; r < 4; ++r) {
            float xv = xs[ng * 4 + r][k];
#pragma unroll
            for (int j = 0; j < 8; ++j) acc[r][j] = fmaf(xv, wv[j], acc[r][j]);
        }
    }
#pragma unroll
    for (int r = 0; r < 4; ++r) {
        int gn = n0 + ng * 4 + r;
        if (gn < N) {
            float4* dst = reinterpret_cast<float4*>(&g_H2[gn * 32 + cg * 8]);
            dst[0] = make_float4(acc[r][0], acc[r][1], acc[r][2], acc[r][3]);
            dst[1] = make_float4(acc[r][4], acc[r][5], acc[r][6], acc[r][7]);
        }
    }
}

// ---------------- L6: layer-2 agg: quarter-warp, x2-unrolled -----------------
__global__ void k_agg2(const float* __restrict__ b2, float* __restrict__ out, int N) {
    int warp = (blockIdx.x * blockDim.x + threadIdx.x) >> 5;
    int lane = threadIdx.x & 31;
    int q = lane >> 3;
    int hl = lane & 7;
    int node = warp * 4 + q;
    if (node >= N) return;
    int beg = g_rowptr[node], end = g_rowptr[node + 1];
    int ch = hl * 4;
    float adv = g_ad2[node];

    float s = 0.f;
    float a0 = 0.f, a1 = 0.f, a2 = 0.f, a3 = 0.f;
    int p = beg;
    for (; p + 1 < end; p += 2) {
        int s0 = g_csrsrc[p];
        int s1 = g_csrsrc[p + 1];
        float e0 = __ldg(&g_as2[s0]) + adv;
        float e1 = __ldg(&g_as2[s1]) + adv;
        float4 h0 = *reinterpret_cast<const float4*>(&g_H2[s0 * 32 + ch]);
        float4 h1 = *reinterpret_cast<const float4*>(&g_H2[s1 * 32 + ch]);
        float w0 = __expf(fmaxf(e0, 0.2f * e0));
        float w1v = __expf(fmaxf(e1, 0.2f * e1));
        s += w0;
        a0 = fmaf(w0, h0.x, a0);
        a1 = fmaf(w0, h0.y, a1);
        a2 = fmaf(w0, h0.z, a2);
        a3 = fmaf(w0, h0.w, a3);
        s += w1v;
        a0 = fmaf(w1v, h1.x, a0);
        a1 = fmaf(w1v, h1.y, a1);
        a2 = fmaf(w1v, h1.z, a2);
        a3 = fmaf(w1v, h1.w, a3);
    }
    if (p < end) {
        int s0 = g_csrsrc[p];
        float e0 = __ldg(&g_as2[s0]) + adv;
        float4 h0 = *reinterpret_cast<const float4*>(&g_H2[s0 * 32 + ch]);
        float w0 = __expf(fmaxf(e0, 0.2f * e0));
        s += w0;
        a0 = fmaf(w0, h0.x, a0);
        a1 = fmaf(w0, h0.y, a1);
        a2 = fmaf(w0, h0.z, a2);
        a3 = fmaf(w0, h0.w, a3);
    }
    float inv = 1.f / (s + 1e-16f);
    float4 bb = *reinterpret_cast<const float4*>(&b2[ch]);
    float4 o;
    o.x = fmaf(a0, inv, bb.x);
    o.y = fmaf(a1, inv, bb.y);
    o.z = fmaf(a2, inv, bb.z);
    o.w = fmaf(a3, inv, bb.w);
    *reinterpret_cast<float4*>(&out[node * 32 + ch]) = o;
}

// ---------------- launch -----------------------------------------------------
extern "C" void kernel_launch(void* const* d_in, const int* in_sizes, int n_in,
                              void* d_out, int out_size) {
    const float* x      = (const float*)d_in[0];
    const int*   ei     = (const int*)  d_in[1];
    const float* W1     = (const float*)d_in[2];
    const float* a_src1 = (const float*)d_in[3];
    const float* a_dst1 = (const float*)d_in[4];
    const float* b1     = (const float*)d_in[5];
    const float* W2     = (const float*)d_in[6];
    const float* a_src2 = (const float*)d_in[7];
    const float* a_dst2 = (const float*)d_in[8];
    const float* b2     = (const float*)d_in[9];

    int N = in_sizes[0] / 128;
    int E = in_sizes[1] / 2;
    int nb = (N + 1023) / 1024;

    int gemmBlocks = (N + 127) / 128;
    int histBlocks = 1184;
    int aggWarps = (N + 3) / 4;          // 4 nodes per warp

    // L1: GEMM1(+alphas1) overlapped with edge histogram
    k_gemm1_hist<<<gemmBlocks + histBlocks, 256>>>(x, W1, a_src1, a_dst1, ei, N, E, gemmBlocks);
    // L2: single-launch scan (device barrier) + v2 projections
    k_scan_fused<<<nb + 1, 1024>>>(W2, a_src2, a_dst2, N, nb);
    // L3: CSR fill + layer-1 edge weights
    k_fillw<<<(E + 255) / 256, 256>>>(ei, E);
    // L4: layer-1 aggregation (+elu, +as2/ad2)
    k_agg1<<<(aggWarps * 32 + 255) / 256, 256>>>(b1, N);
    // L5: GEMM2
    k_gemm2<<<(N + 127) / 128, 128>>>(W2, N);
    // L6: layer-2 aggregation (inline w2)
    k_agg2<<<(aggWarps * 32 + 255) / 256, 256>>>(b2, (float*)d_out, N);
}